// round 11
// baseline (speedup 1.0000x reference)
#include <cuda_runtime.h>
#include <cuda_bf16.h>
#include <cstdint>

#define BB 32
#define SS 16
#define FF 2048
#define GT 16       // g-tiles per batch (128 g each)
#define GTILE 128
#define NFT 16

// Scratch (device globals — no allocations allowed)
__device__ float g_Cpart[BB * GT * SS * SS];  // Gram partials per g-tile
__device__ float g_Dpart[BB * GT * SS];       // D partials per g-tile
__device__ float g_E[BB * SS * SS];           // folded gate weights  [b][s*16+so]
__device__ float g_const[BB * SS];            // folded gate constants [b][so]
__device__ __align__(16) uint4 g_dataB[BB * FF * 4];  // pre-packed B frags (4 MB)

// pack two fp32 -> bf16x2 {lo=v0, hi=v1}
__device__ __forceinline__ uint32_t pack_bf2(float v0, float v1) {
    uint32_t r;
    asm("cvt.rn.bf16x2.f32 %0, %1, %2;" : "=r"(r) : "f"(v1), "f"(v0));
    return r;
}
__device__ __forceinline__ float bf_res(float y) {
    return y - __bfloat162float(__float2bfloat16(y));
}
__device__ __forceinline__ void mk_pair(float v0, float v1, uint32_t& hi, uint32_t& lo) {
    hi = pack_bf2(v0, v1);
    lo = pack_bf2(bf_res(v0), bf_res(v1));
}
__device__ __forceinline__ void mma_bf16(float* d, const uint32_t* a, uint32_t b0, uint32_t b1) {
    asm volatile(
        "mma.sync.aligned.m16n8k16.row.col.f32.bf16.bf16.f32 "
        "{%0,%1,%2,%3}, {%4,%5,%6,%7}, {%8,%9}, {%0,%1,%2,%3};"
        : "+f"(d[0]), "+f"(d[1]), "+f"(d[2]), "+f"(d[3])
        : "r"(a[0]), "r"(a[1]), "r"(a[2]), "r"(a[3]), "r"(b0), "r"(b1));
}

// ---------------------------------------------------------------------------
// Kernel 0: pre-pack data -> hi/lo bf16x2 fragment words, quad-swizzled.
// ---------------------------------------------------------------------------
__global__ void __launch_bounds__(256) convert_kernel(const float* __restrict__ data) {
    int gid = blockIdx.x * 256 + threadIdx.x;  // b*2048 + f
    int b = gid >> 11, f = gid & 2047;
    float v[16];
#pragma unroll
    for (int s = 0; s < 16; s++) v[s] = data[(b * SS + s) * FF + f];
    uint4* out = g_dataB + gid * 4;
    int x = f & 3;
#pragma unroll
    for (int h = 0; h < 2; h++) {
        float a0 = v[4 * h], a1 = v[4 * h + 1], a2 = v[4 * h + 2], a3 = v[4 * h + 3];
        float c0 = v[4 * h + 8], c1 = v[4 * h + 9], c2 = v[4 * h + 10], c3 = v[4 * h + 11];
        uint4 qh = make_uint4(pack_bf2(a0, a1), pack_bf2(c0, c1),
                              pack_bf2(a2, a3), pack_bf2(c2, c3));
        uint4 ql = make_uint4(pack_bf2(bf_res(a0), bf_res(a1)), pack_bf2(bf_res(c0), bf_res(c1)),
                              pack_bf2(bf_res(a2), bf_res(a3)), pack_bf2(bf_res(c2), bf_res(c3)));
        out[h ^ x] = qh;
        out[(2 + h) ^ x] = ql;
    }
}

// ---------------------------------------------------------------------------
// Kernel 1: exp-sum + fused gram + LSE + D-partials. Barrier-free mainloop,
// split MMA dependency chains (m1 || m2) to cut latency before ex2.
// ---------------------------------------------------------------------------
__global__ void __launch_bounds__(256, 3) expsum_mma(const float* __restrict__ attn) {
    __shared__ float attnS[SS][129];
    __shared__ float red[4][GTILE];

    int tid = threadIdx.x, wid = tid >> 5, lane = tid & 31;
    int wg = wid >> 2, wf = wid & 3;
    int b = blockIdx.x, gt = blockIdx.y;
    int gbase = gt * GTILE;

#pragma unroll
    for (int i = 0; i < 8; i++) {
        int idx = tid + i * 256;
        int s = idx >> 7, gi = idx & 127;
        attnS[s][gi] = attn[(b * SS + s) * FF + gbase + gi];
    }
    __syncthreads();

    // A fragments: 4 m-tiles x 4 regs, hi+lo, scaled by log2e.
    const float LOG2E = 1.442695040888963f;
    int m0 = lane >> 2, k0 = (lane & 3) * 2;
    uint32_t a_hi[4][4], a_lo[4][4];
#pragma unroll
    for (int mt = 0; mt < 4; mt++) {
        int gi = (wg * 4 + mt) * 16 + m0;
        mk_pair(attnS[k0][gi] * LOG2E,     attnS[k0 + 1][gi] * LOG2E,     a_hi[mt][0], a_lo[mt][0]);
        mk_pair(attnS[k0][gi + 8] * LOG2E, attnS[k0 + 1][gi + 8] * LOG2E, a_hi[mt][1], a_lo[mt][1]);
        mk_pair(attnS[k0 + 8][gi] * LOG2E, attnS[k0 + 9][gi] * LOG2E,     a_hi[mt][2], a_lo[mt][2]);
        mk_pair(attnS[k0 + 8][gi + 8] * LOG2E, attnS[k0 + 9][gi + 8] * LOG2E, a_hi[mt][3], a_lo[mt][3]);
    }

    float acc[8];
#pragma unroll
    for (int i = 0; i < 8; i++) acc[i] = 0.f;

    int nidx = lane >> 2, kq = lane & 3;
    const uint2* Bp = (const uint2*)g_dataB + (size_t)b * FF * 8;
    int qh_idx = ((((kq >> 1)) ^ (nidx & 3)) << 1) + (kq & 1);
    int ql_idx = qh_idx ^ 4;

    for (int t = 0; t < NFT; t++) {
        uint2 bh[4], bl[4];
#pragma unroll
        for (int j = 0; j < 4; j++) {
            int row = t * GTILE + (wf * 4 + j) * 8 + nidx;
            bh[j] = __ldg(Bp + row * 8 + qh_idx);
            bl[j] = __ldg(Bp + row * 8 + ql_idx);
        }
#pragma unroll
        for (int j = 0; j < 4; j++) {
#pragma unroll
            for (int mt = 0; mt < 4; mt++) {
                float m1[4] = {0.f, 0.f, 0.f, 0.f};
                float m2[4] = {0.f, 0.f, 0.f, 0.f};
                mma_bf16(m1, a_lo[mt], bh[j].x, bh[j].y);   // independent chain
                mma_bf16(m2, a_hi[mt], bl[j].x, bl[j].y);   // chain 2 (2 serial)
                mma_bf16(m2, a_hi[mt], bh[j].x, bh[j].y);
                float e0, e1, e2, e3;
                asm("ex2.approx.f32 %0, %1;" : "=f"(e0) : "f"(m1[0] + m2[0]));
                asm("ex2.approx.f32 %0, %1;" : "=f"(e1) : "f"(m1[1] + m2[1]));
                asm("ex2.approx.f32 %0, %1;" : "=f"(e2) : "f"(m1[2] + m2[2]));
                asm("ex2.approx.f32 %0, %1;" : "=f"(e3) : "f"(m1[3] + m2[3]));
                acc[2 * mt] += e0 + e1;
                acc[2 * mt + 1] += e2 + e3;
            }
        }
    }

    // quad-reduce (lanes sharing a D row), write per-(wf) partial rows
#pragma unroll
    for (int i = 0; i < 8; i++) {
        acc[i] += __shfl_xor_sync(0xffffffffu, acc[i], 1);
        acc[i] += __shfl_xor_sync(0xffffffffu, acc[i], 2);
    }
    if (kq == 0) {
#pragma unroll
        for (int mt = 0; mt < 4; mt++) {
            red[wf][(wg * 4 + mt) * 16 + m0] = acc[2 * mt];
            red[wf][(wg * 4 + mt) * 16 + m0 + 8] = acc[2 * mt + 1];
        }
    }
    __syncthreads();
    if (tid < GTILE) {
        float s = red[0][tid] + red[1][tid] + red[2][tid] + red[3][tid];
        red[0][tid] = logf(s);
    }
    __syncthreads();

    // D partials: warp w handles s = 2w, 2w+1 over this g-tile
#pragma unroll
    for (int hh = 0; hh < 2; hh++) {
        int s2 = wid * 2 + hh;
        float p = 0.f;
#pragma unroll
        for (int k = 0; k < 4; k++) p = fmaf(red[0][lane + 32 * k], attnS[s2][lane + 32 * k], p);
#pragma unroll
        for (int o = 16; o; o >>= 1) p += __shfl_xor_sync(0xffffffffu, p, o);
        if (lane == 0) g_Dpart[(b * GT + gt) * SS + s2] = p;
    }

    // Gram partial for this g-tile: thread = (s1,s2)
    {
        int s1 = tid >> 4, s2 = tid & 15;
        float a = 0.f;
#pragma unroll 4
        for (int g = 0; g < GTILE; g++) a = fmaf(attnS[s1][g], attnS[s2][g], a);
        g_Cpart[(b * GT + gt) * 256 + tid] = a;
    }
}

// ---------------------------------------------------------------------------
// Kernel 2: combine (once per batch) -> g_E, g_const.
// ---------------------------------------------------------------------------
__global__ void __launch_bounds__(256) combine_kernel(const float* __restrict__ Wm,
                                                      const float* __restrict__ bias) {
    int bb = blockIdx.x;
    int tid = threadIdx.x;
    __shared__ float Csm[256], Dsm[16];
    {
        float cs = 0.f;
#pragma unroll
        for (int c = 0; c < GT; c++) cs += g_Cpart[(bb * GT + c) * 256 + tid];
        Csm[tid] = cs;
    }
    if (tid < 16) {
        float d = 0.f;
#pragma unroll
        for (int gt = 0; gt < GT; gt++) d += g_Dpart[(bb * GT + gt) * SS + tid];
        Dsm[tid] = d;
    }
    __syncthreads();
    {
        int s = tid >> 4, so = tid & 15;
        float e = Wm[so * 32 + 16 + s];
#pragma unroll
        for (int k = 0; k < SS; k++) e = fmaf(Csm[s * SS + k], Wm[so * 32 + k], e);
        g_E[bb * 256 + s * 16 + so] = e;
    }
    if (tid < 16) {
        float c = bias[tid];
#pragma unroll
        for (int k = 0; k < SS; k++) c = fmaf(-Dsm[k], Wm[tid * 32 + k], c);
        g_const[bb * SS + tid] = c;
    }
}

// ---------------------------------------------------------------------------
// Kernel 3: final output. din staged in smem (1x LDG), low regs, grid (32,16).
// ---------------------------------------------------------------------------
__global__ void __launch_bounds__(256) final_kernel(const float* __restrict__ data,
                                                    float* __restrict__ out) {
    int bb = blockIdx.x, q = blockIdx.y;
    int tid = threadIdx.x;
    __shared__ float4 dinS[SS][32];
    __shared__ float Esm[256], Km[16];

    const float4* d4 = (const float4*)data;
    float4* o4 = (float4*)out;
    {
        int i0 = tid, i1 = tid + 256;
        int s0 = i0 >> 5, c0 = i0 & 31;
        int s1 = i1 >> 5, c1 = i1 & 31;
        dinS[s0][c0] = d4[(bb * SS + s0) * (FF / 4) + q * 32 + c0];
        dinS[s1][c1] = d4[(bb * SS + s1) * (FF / 4) + q * 32 + c1];
    }
    Esm[tid] = g_E[bb * 256 + tid];
    if (tid < 16) Km[tid] = g_const[bb * SS + tid];
    __syncthreads();

    int col = tid & 31, oct = tid >> 5;
    int c = q * 32 + col;
#pragma unroll
    for (int i = 0; i < 2; i++) {
        int so = oct * 2 + i;
        float k0 = Km[so];
        float zx = k0, zy = k0, zz = k0, zw = k0;
#pragma unroll
        for (int s = 0; s < SS; s++) {
            float4 dv = dinS[s][col];
            float e = Esm[s * 16 + so];
            zx = fmaf(dv.x, e, zx);
            zy = fmaf(dv.y, e, zy);
            zz = fmaf(dv.z, e, zz);
            zw = fmaf(dv.w, e, zw);
        }
        float gx = 1.f / (1.f + __expf(-zx));
        float gy = 1.f / (1.f + __expf(-zy));
        float gz = 1.f / (1.f + __expf(-zz));
        float gw = 1.f / (1.f + __expf(-zw));
        int row = so * 32 + bb;
        float4 dv = d4[row * (FF / 4) + c];
        float4 ov;
        ov.x = gx * dv.x;
        ov.y = gy * dv.y;
        ov.z = gz * dv.z;
        ov.w = gw * dv.w;
        o4[row * (FF / 4) + c] = ov;
    }
}

// ---------------------------------------------------------------------------
extern "C" void kernel_launch(void* const* d_in, const int* in_sizes, int n_in,
                              void* d_out, int out_size) {
    const float* data = (const float*)d_in[0];
    const float* attn = (const float*)d_in[1];
    const float* W = (const float*)d_in[2];
    const float* bias = (const float*)d_in[3];
    float* out = (float*)d_out;

    convert_kernel<<<BB * FF / 256, 256>>>(data);
    expsum_mma<<<dim3(BB, GT), 256>>>(attn);
    combine_kernel<<<BB, 256>>>(W, bias);
    final_kernel<<<dim3(BB, GT), 256>>>(data, out);
}

// round 14
// speedup vs baseline: 1.0990x; 1.0990x over previous
#include <cuda_runtime.h>
#include <cuda_bf16.h>
#include <cstdint>

#define BB 32
#define SS 16
#define FF 2048
#define GT 16       // g-tiles per batch (128 g each)
#define GTILE 128
#define NFT 16

// Scratch (device globals — no allocations allowed)
__device__ float g_Cpart[BB * GT * SS * SS];  // Gram partials per g-tile
__device__ float g_Dpart[BB * GT * SS];       // D partials per g-tile
__device__ float g_E[BB * SS * SS];           // folded gate weights  [b][s*16+so]
__device__ float g_const[BB * SS];            // folded gate constants [b][so]
__device__ __align__(16) uint4 g_dataB[BB * FF * 4];  // pre-packed B frags (4 MB)

// pack two fp32 -> bf16x2 {lo=v0, hi=v1}
__device__ __forceinline__ uint32_t pack_bf2(float v0, float v1) {
    uint32_t r;
    asm("cvt.rn.bf16x2.f32 %0, %1, %2;" : "=r"(r) : "f"(v1), "f"(v0));
    return r;
}
__device__ __forceinline__ float bf_res(float y) {
    return y - __bfloat162float(__float2bfloat16(y));
}
__device__ __forceinline__ void mk_pair(float v0, float v1, uint32_t& hi, uint32_t& lo) {
    hi = pack_bf2(v0, v1);
    lo = pack_bf2(bf_res(v0), bf_res(v1));
}
__device__ __forceinline__ void mma_bf16(float* d, const uint32_t* a, uint32_t b0, uint32_t b1) {
    asm volatile(
        "mma.sync.aligned.m16n8k16.row.col.f32.bf16.bf16.f32 "
        "{%0,%1,%2,%3}, {%4,%5,%6,%7}, {%8,%9}, {%0,%1,%2,%3};"
        : "+f"(d[0]), "+f"(d[1]), "+f"(d[2]), "+f"(d[3])
        : "r"(a[0]), "r"(a[1]), "r"(a[2]), "r"(a[3]), "r"(b0), "r"(b1));
}

// ---------------------------------------------------------------------------
// Kernel 0: pre-pack data -> hi/lo bf16x2 fragment words, quad-swizzled.
// ---------------------------------------------------------------------------
__global__ void __launch_bounds__(256) convert_kernel(const float* __restrict__ data) {
    int gid = blockIdx.x * 256 + threadIdx.x;  // b*2048 + f
    int b = gid >> 11, f = gid & 2047;
    float v[16];
#pragma unroll
    for (int s = 0; s < 16; s++) v[s] = data[(b * SS + s) * FF + f];
    uint4* out = g_dataB + gid * 4;
    int x = f & 3;
#pragma unroll
    for (int h = 0; h < 2; h++) {
        float a0 = v[4 * h], a1 = v[4 * h + 1], a2 = v[4 * h + 2], a3 = v[4 * h + 3];
        float c0 = v[4 * h + 8], c1 = v[4 * h + 9], c2 = v[4 * h + 10], c3 = v[4 * h + 11];
        uint4 qh = make_uint4(pack_bf2(a0, a1), pack_bf2(c0, c1),
                              pack_bf2(a2, a3), pack_bf2(c2, c3));
        uint4 ql = make_uint4(pack_bf2(bf_res(a0), bf_res(a1)), pack_bf2(bf_res(c0), bf_res(c1)),
                              pack_bf2(bf_res(a2), bf_res(a3)), pack_bf2(bf_res(c2), bf_res(c3)));
        out[h ^ x] = qh;
        out[(2 + h) ^ x] = ql;
    }
}

// ---------------------------------------------------------------------------
// Kernel 1: exp-sum + fused gram + LSE + D-partials. Barrier-free mainloop
// (R10 serial 3-MMA chain — the m1/m2 split regressed and was reverted).
// ---------------------------------------------------------------------------
__global__ void __launch_bounds__(256, 3) expsum_mma(const float* __restrict__ attn) {
    __shared__ float attnS[SS][129];
    __shared__ float red[4][GTILE];

    int tid = threadIdx.x, wid = tid >> 5, lane = tid & 31;
    int wg = wid >> 2, wf = wid & 3;
    int b = blockIdx.x, gt = blockIdx.y;
    int gbase = gt * GTILE;

#pragma unroll
    for (int i = 0; i < 8; i++) {
        int idx = tid + i * 256;
        int s = idx >> 7, gi = idx & 127;
        attnS[s][gi] = attn[(b * SS + s) * FF + gbase + gi];
    }
    __syncthreads();

    // A fragments: 4 m-tiles x 4 regs, hi+lo, scaled by log2e.
    const float LOG2E = 1.442695040888963f;
    int m0 = lane >> 2, k0 = (lane & 3) * 2;
    uint32_t a_hi[4][4], a_lo[4][4];
#pragma unroll
    for (int mt = 0; mt < 4; mt++) {
        int gi = (wg * 4 + mt) * 16 + m0;
        mk_pair(attnS[k0][gi] * LOG2E,     attnS[k0 + 1][gi] * LOG2E,     a_hi[mt][0], a_lo[mt][0]);
        mk_pair(attnS[k0][gi + 8] * LOG2E, attnS[k0 + 1][gi + 8] * LOG2E, a_hi[mt][1], a_lo[mt][1]);
        mk_pair(attnS[k0 + 8][gi] * LOG2E, attnS[k0 + 9][gi] * LOG2E,     a_hi[mt][2], a_lo[mt][2]);
        mk_pair(attnS[k0 + 8][gi + 8] * LOG2E, attnS[k0 + 9][gi + 8] * LOG2E, a_hi[mt][3], a_lo[mt][3]);
    }

    float acc[8];
#pragma unroll
    for (int i = 0; i < 8; i++) acc[i] = 0.f;

    int nidx = lane >> 2, kq = lane & 3;
    const uint2* Bp = (const uint2*)g_dataB + (size_t)b * FF * 8;
    int qh_idx = ((((kq >> 1)) ^ (nidx & 3)) << 1) + (kq & 1);
    int ql_idx = qh_idx ^ 4;

    for (int t = 0; t < NFT; t++) {
        uint2 bh[4], bl[4];
#pragma unroll
        for (int j = 0; j < 4; j++) {
            int row = t * GTILE + (wf * 4 + j) * 8 + nidx;
            bh[j] = __ldg(Bp + row * 8 + qh_idx);
            bl[j] = __ldg(Bp + row * 8 + ql_idx);
        }
#pragma unroll
        for (int j = 0; j < 4; j++) {
#pragma unroll
            for (int mt = 0; mt < 4; mt++) {
                float d[4] = {0.f, 0.f, 0.f, 0.f};
                mma_bf16(d, a_lo[mt], bh[j].x, bh[j].y);
                mma_bf16(d, a_hi[mt], bl[j].x, bl[j].y);
                mma_bf16(d, a_hi[mt], bh[j].x, bh[j].y);
                float e0, e1, e2, e3;
                asm("ex2.approx.f32 %0, %1;" : "=f"(e0) : "f"(d[0]));
                asm("ex2.approx.f32 %0, %1;" : "=f"(e1) : "f"(d[1]));
                asm("ex2.approx.f32 %0, %1;" : "=f"(e2) : "f"(d[2]));
                asm("ex2.approx.f32 %0, %1;" : "=f"(e3) : "f"(d[3]));
                acc[2 * mt] += e0 + e1;
                acc[2 * mt + 1] += e2 + e3;
            }
        }
    }

    // quad-reduce (lanes sharing a D row), write per-(wf) partial rows
#pragma unroll
    for (int i = 0; i < 8; i++) {
        acc[i] += __shfl_xor_sync(0xffffffffu, acc[i], 1);
        acc[i] += __shfl_xor_sync(0xffffffffu, acc[i], 2);
    }
    if (kq == 0) {
#pragma unroll
        for (int mt = 0; mt < 4; mt++) {
            red[wf][(wg * 4 + mt) * 16 + m0] = acc[2 * mt];
            red[wf][(wg * 4 + mt) * 16 + m0 + 8] = acc[2 * mt + 1];
        }
    }
    __syncthreads();
    if (tid < GTILE) {
        float s = red[0][tid] + red[1][tid] + red[2][tid] + red[3][tid];
        red[0][tid] = logf(s);
    }
    __syncthreads();

    // D partials: warp w handles s = 2w, 2w+1 over this g-tile
#pragma unroll
    for (int hh = 0; hh < 2; hh++) {
        int s2 = wid * 2 + hh;
        float p = 0.f;
#pragma unroll
        for (int k = 0; k < 4; k++) p = fmaf(red[0][lane + 32 * k], attnS[s2][lane + 32 * k], p);
#pragma unroll
        for (int o = 16; o; o >>= 1) p += __shfl_xor_sync(0xffffffffu, p, o);
        if (lane == 0) g_Dpart[(b * GT + gt) * SS + s2] = p;
    }

    // Gram partial for this g-tile: thread = (s1,s2)
    {
        int s1 = tid >> 4, s2 = tid & 15;
        float a = 0.f;
#pragma unroll 4
        for (int g = 0; g < GTILE; g++) a = fmaf(attnS[s1][g], attnS[s2][g], a);
        g_Cpart[(b * GT + gt) * 256 + tid] = a;
    }
}

// ---------------------------------------------------------------------------
// Kernel 2: combine (once per batch) -> g_E, g_const.
// ---------------------------------------------------------------------------
__global__ void __launch_bounds__(256) combine_kernel(const float* __restrict__ Wm,
                                                      const float* __restrict__ bias) {
    int bb = blockIdx.x;
    int tid = threadIdx.x;
    __shared__ float Csm[256], Dsm[16];
    {
        float cs = 0.f;
#pragma unroll
        for (int c = 0; c < GT; c++) cs += g_Cpart[(bb * GT + c) * 256 + tid];
        Csm[tid] = cs;
    }
    if (tid < 16) {
        float d = 0.f;
#pragma unroll
        for (int gt = 0; gt < GT; gt++) d += g_Dpart[(bb * GT + gt) * SS + tid];
        Dsm[tid] = d;
    }
    __syncthreads();
    {
        int s = tid >> 4, so = tid & 15;
        float e = Wm[so * 32 + 16 + s];
#pragma unroll
        for (int k = 0; k < SS; k++) e = fmaf(Csm[s * SS + k], Wm[so * 32 + k], e);
        g_E[bb * 256 + s * 16 + so] = e;
    }
    if (tid < 16) {
        float c = bias[tid];
#pragma unroll
        for (int k = 0; k < SS; k++) c = fmaf(-Dsm[k], Wm[tid * 32 + k], c);
        g_const[bb * SS + tid] = c;
    }
}

// ---------------------------------------------------------------------------
// Kernel 3: final output, 512 thr/block, one (so, col) output per thread.
// Block (bb, q): stages 16x32 din float4 tile in smem (1 LDG.128/thread),
// then thread (so = tid>>5, col = tid&31) computes one output float4.
// ---------------------------------------------------------------------------
__global__ void __launch_bounds__(512) final_kernel(const float* __restrict__ data,
                                                    float* __restrict__ out) {
    int bb = blockIdx.x, q = blockIdx.y;
    int tid = threadIdx.x;
    __shared__ float4 dinS[SS][32];
    __shared__ float Esm[256], Km[16];

    const float4* d4 = (const float4*)data;
    float4* o4 = (float4*)out;
    int s = tid >> 5, col = tid & 31;
    dinS[s][col] = d4[(bb * SS + s) * (FF / 4) + q * 32 + col];
    if (tid < 256) Esm[tid] = g_E[bb * 256 + tid];
    if (tid < 16) Km[tid] = g_const[bb * SS + tid];
    __syncthreads();

    int so = s;  // warp-uniform -> Esm reads are broadcasts
    float k0 = Km[so];
    float zx = k0, zy = k0, zz = k0, zw = k0;
#pragma unroll
    for (int s2 = 0; s2 < SS; s2++) {
        float4 dv = dinS[s2][col];
        float e = Esm[s2 * 16 + so];
        zx = fmaf(dv.x, e, zx);
        zy = fmaf(dv.y, e, zy);
        zz = fmaf(dv.z, e, zz);
        zw = fmaf(dv.w, e, zw);
    }
    float gx = 1.f / (1.f + __expf(-zx));
    float gy = 1.f / (1.f + __expf(-zy));
    float gz = 1.f / (1.f + __expf(-zz));
    float gw = 1.f / (1.f + __expf(-zw));
    int row = so * 32 + bb;
    int c = q * 32 + col;
    float4 dv = d4[row * (FF / 4) + c];
    float4 ov;
    ov.x = gx * dv.x;
    ov.y = gy * dv.y;
    ov.z = gz * dv.z;
    ov.w = gw * dv.w;
    o4[row * (FF / 4) + c] = ov;
}

// ---------------------------------------------------------------------------
extern "C" void kernel_launch(void* const* d_in, const int* in_sizes, int n_in,
                              void* d_out, int out_size) {
    const float* data = (const float*)d_in[0];
    const float* attn = (const float*)d_in[1];
    const float* W = (const float*)d_in[2];
    const float* bias = (const float*)d_in[3];
    float* out = (float*)d_out;

    convert_kernel<<<BB * FF / 256, 256>>>(data);
    expsum_mma<<<dim3(BB, GT), 256>>>(attn);
    combine_kernel<<<BB, 256>>>(W, bias);
    final_kernel<<<dim3(BB, GT), 512>>>(data, out);
}